// round 8
// baseline (speedup 1.0000x reference)
#include <cuda_runtime.h>
#include <stdint.h>

// Problem constants (fixed by the reference).
static constexpr int P  = 16;    // permutations
static constexpr int B  = 4096;  // batch
static constexpr int NB = 256;   // blocks per permutation (D/STEP)
static constexpr int D  = 1024;  // feature dim
static constexpr int ROWS = 8;   // batch rows per thread in main kernel

// Scratch: perm table extracted from T each call (no caching allowed).
__device__ int g_perm[P * NB];

// ---------------------------------------------------------------------------
// Kernel 1: extract the block permutation from the dense T matrices.
// T[i, 4r:4r+4, 4c:4c+4] = I  when perm_i[r] = c.
// One warp per (i, r): lanes scan c, exactly one lane finds the 1.0.
// ---------------------------------------------------------------------------
__global__ void extract_perms_kernel(const float* __restrict__ T) {
    int warp_global = (blockIdx.x * blockDim.x + threadIdx.x) >> 5;
    int lane = threadIdx.x & 31;
    if (warp_global >= P * NB) return;
    int i = warp_global >> 8;      // permutation index
    int r = warp_global & (NB - 1);
    const float* row = T + ((size_t)i * D + 4 * r) * D;  // row o = 4r of T[i]
#pragma unroll
    for (int k = 0; k < NB / 32; ++k) {
        int c = lane + 32 * k;
        // exactly one c has a 1.0 on this row at column 4c
        if (row[4 * c] > 0.5f) g_perm[warp_global] = c;
    }
}

// ---------------------------------------------------------------------------
// Kernel 2: apply the gather.
//   out[(g*B + b), :]  with column blocks permuted by perm[indices[g]].
// float4 granularity (STEP=4, 16B aligned).
// Grid order: group index INNER so the 16 blocks reading the same x rows are
// co-resident -> x stays L2-hot. Streaming stores (__stcs) keep the 256MB
// write stream from evicting x.
// One block = 256 threads (one per output float4 column) x ROWS batch rows.
// ---------------------------------------------------------------------------
__global__ void __launch_bounds__(256)
permute_gather_kernel(const float4* __restrict__ x4,
                      const int*    __restrict__ indices,
                      float4*       __restrict__ out4) {
    const int tid = threadIdx.x;                 // output column block 0..255
    const int grp     = blockIdx.x % P;          // inner: group (x-row reuse)
    const int b_chunk = blockIdx.x / P;          // outer: batch chunk
    const int b0 = b_chunk * ROWS;

    const int j    = __ldg(&indices[grp]);       // which permutation
    const int pblk = g_perm[j * NB + tid];       // source column block

    const float4* src = x4 + pblk;                                   // + b*NB
    float4* dst = out4 + ((size_t)grp * B + b0) * NB + tid;          // + k*NB

    float4 v[ROWS];
#pragma unroll
    for (int k = 0; k < ROWS; ++k)
        v[k] = __ldg(src + (size_t)(b0 + k) * NB);
#pragma unroll
    for (int k = 0; k < ROWS; ++k)
        __stcs(dst + (size_t)k * NB, v[k]);      // evict-first streaming store
}

// ---------------------------------------------------------------------------
// Launch
// ---------------------------------------------------------------------------
extern "C" void kernel_launch(void* const* d_in, const int* in_sizes, int n_in,
                              void* d_out, int out_size) {
    const float* x   = (const float*)d_in[0];   // [B, D] fp32
    const float* T   = (const float*)d_in[1];   // [P, D, D] fp32
    const int*   idx = (const int*)d_in[2];     // [P] int32
    float* out = (float*)d_out;                 // [P*B, D] fp32

    // 1) Extract permutations: P*NB = 4096 warps -> 512 blocks x 256 threads.
    extract_perms_kernel<<<(P * NB * 32 + 255) / 256, 256>>>(T);

    // 2) Gather: (B/ROWS) batch chunks x P groups, group-inner ordering.
    permute_gather_kernel<<<(B / ROWS) * P, 256>>>(
        (const float4*)x, idx, (float4*)out);
}

// round 9
// speedup vs baseline: 1.0213x; 1.0213x over previous
#include <cuda_runtime.h>
#include <stdint.h>

// Problem constants (fixed by the reference).
static constexpr int P  = 16;    // permutations
static constexpr int B  = 4096;  // batch
static constexpr int NB = 256;   // blocks per permutation (D/STEP)
static constexpr int D  = 1024;  // feature dim
static constexpr int ROWS = 8;   // batch rows per thread in main kernel

// Scratch: perm table extracted from T each call (no caching allowed).
__device__ int g_perm[P * NB];

// ---------------------------------------------------------------------------
// Kernel 1: extract the block permutation from the dense T matrices.
// T[i, 4r:4r+4, 4c:4c+4] = I  when perm_i[r] = c.
// One warp per (i, r): lanes scan c, exactly one lane finds the 1.0.
// ---------------------------------------------------------------------------
__global__ void extract_perms_kernel(const float* __restrict__ T) {
    int warp_global = (blockIdx.x * blockDim.x + threadIdx.x) >> 5;
    int lane = threadIdx.x & 31;
    if (warp_global >= P * NB) return;
    int i = warp_global >> 8;      // permutation index
    int r = warp_global & (NB - 1);
    const float* row = T + ((size_t)i * D + 4 * r) * D;  // row o = 4r of T[i]
#pragma unroll
    for (int k = 0; k < NB / 32; ++k) {
        int c = lane + 32 * k;
        // exactly one c has a 1.0 on this row at column 4c
        if (row[4 * c] > 0.5f) g_perm[warp_global] = c;
    }
}

// ---------------------------------------------------------------------------
// Kernel 2: apply the gather.
//   out[(g*B + b), :]  with column blocks permuted by perm[indices[g]].
// float4 granularity (STEP=4, 16B aligned).
// Grid order: group index INNER so the 16 blocks reading the same x rows are
// co-resident -> x stays L2-hot. Streaming stores (__stcs) keep the 256MB
// write stream from evicting x.
// One block = 256 threads (one per output float4 column) x ROWS batch rows.
// ---------------------------------------------------------------------------
__global__ void __launch_bounds__(256)
permute_gather_kernel(const float4* __restrict__ x4,
                      const int*    __restrict__ indices,
                      float4*       __restrict__ out4) {
    const int tid = threadIdx.x;                 // output column block 0..255
    const int grp     = blockIdx.x % P;          // inner: group (x-row reuse)
    const int b_chunk = blockIdx.x / P;          // outer: batch chunk
    const int b0 = b_chunk * ROWS;

    const int j    = __ldg(&indices[grp]);       // which permutation
    const int pblk = g_perm[j * NB + tid];       // source column block

    const float4* src = x4 + pblk;                                   // + b*NB
    float4* dst = out4 + ((size_t)grp * B + b0) * NB + tid;          // + k*NB

    float4 v[ROWS];
#pragma unroll
    for (int k = 0; k < ROWS; ++k)
        v[k] = __ldg(src + (size_t)(b0 + k) * NB);
#pragma unroll
    for (int k = 0; k < ROWS; ++k)
        __stcs(dst + (size_t)k * NB, v[k]);      // evict-first streaming store
}

// ---------------------------------------------------------------------------
// Launch
// ---------------------------------------------------------------------------
extern "C" void kernel_launch(void* const* d_in, const int* in_sizes, int n_in,
                              void* d_out, int out_size) {
    const float* x   = (const float*)d_in[0];   // [B, D] fp32
    const float* T   = (const float*)d_in[1];   // [P, D, D] fp32
    const int*   idx = (const int*)d_in[2];     // [P] int32
    float* out = (float*)d_out;                 // [P*B, D] fp32

    // 1) Extract permutations: P*NB = 4096 warps -> 512 blocks x 256 threads.
    extract_perms_kernel<<<(P * NB * 32 + 255) / 256, 256>>>(T);

    // 2) Gather: (B/ROWS) batch chunks x P groups, group-inner ordering.
    permute_gather_kernel<<<(B / ROWS) * P, 256>>>(
        (const float4*)x, idx, (float4*)out);
}